// round 16
// baseline (speedup 1.0000x reference)
#include <cuda_runtime.h>

#define N_ROWS  8192
#define N_COLS  32000
#define NV4     (N_COLS / 4)
#define K2      4915              // int(0.6 * int(1.0 * 8192))
#define THREADS 256
#define NFINE   65536
#define QSCALE  2048.0f
#define NB2B    32                // finish-kernel blocks (256 thr each = 8192)

// Scratch (device globals; restored each replay by the last finish block)
__device__ float              g_vals[N_ROWS];
__device__ unsigned int       g_fine[NFINE];      // 256 KB fine histogram
__device__ unsigned int       g_coarse[256];
__device__ unsigned long long g_sum;              // fixed-point 2^32 sum above bin
__device__ float              g_cand[N_ROWS];
__device__ unsigned int       g_candcnt;
__device__ unsigned int       g_done;

__device__ __forceinline__ int quant(float v) {
    int q = (int)(v * QSCALE);
    return max(0, min(q, NFINE - 1));
}
__device__ __forceinline__ unsigned int key_of(float f) {
    unsigned int u = __float_as_uint(f);
    return u ^ ((u & 0x80000000u) ? 0xFFFFFFFFu : 0x80000000u);
}
__device__ __forceinline__ float val_of(unsigned int k) {
    return __uint_as_float((k & 0x80000000u) ? (k ^ 0x80000000u) : ~k);
}
__device__ __forceinline__ long long fixed_of(float v) {
    return (long long)((double)v * 4294967296.0);   // exact, deterministic
}

// ---------------------------------------------------------------------------
// Kernel 1: one block per row, single-pass logsumexp loss (proven 90%-HBM
// mainloop, byte-identical). Tail: loss store + fine/coarse hist atomics.
// ---------------------------------------------------------------------------
__global__ __launch_bounds__(THREADS) void loss_kernel(const float* __restrict__ x,
                                                       const int* __restrict__ tgt) {
    const int row = blockIdx.x;
    const float4* __restrict__ rp =
        reinterpret_cast<const float4*>(x + (size_t)row * N_COLS);

    float s0 = 0.f, s1 = 0.f, s2 = 0.f, s3 = 0.f;
    int i = threadIdx.x;
    for (; i + 3 * THREADS < NV4; i += 4 * THREADS) {
        const float4 a = __ldcs(rp + i);
        const float4 b = __ldcs(rp + i + THREADS);
        const float4 c = __ldcs(rp + i + 2 * THREADS);
        const float4 d = __ldcs(rp + i + 3 * THREADS);
        s0 += (__expf(a.x) + __expf(a.y)) + (__expf(a.z) + __expf(a.w));
        s1 += (__expf(b.x) + __expf(b.y)) + (__expf(b.z) + __expf(b.w));
        s2 += (__expf(c.x) + __expf(c.y)) + (__expf(c.z) + __expf(c.w));
        s3 += (__expf(d.x) + __expf(d.y)) + (__expf(d.z) + __expf(d.w));
    }
    for (; i < NV4; i += THREADS) {
        const float4 a = __ldcs(rp + i);
        s0 += (__expf(a.x) + __expf(a.y)) + (__expf(a.z) + __expf(a.w));
    }

    float s = (s0 + s1) + (s2 + s3);
    #pragma unroll
    for (int off = 16; off; off >>= 1)
        s += __shfl_xor_sync(0xffffffffu, s, off);

    __shared__ float sm_s[THREADS / 32];
    const int warp = threadIdx.x >> 5;
    const int lane = threadIdx.x & 31;
    if (lane == 0) sm_s[warp] = s;
    __syncthreads();

    if (threadIdx.x == 0) {
        float t = 0.f;
        #pragma unroll
        for (int w = 0; w < THREADS / 32; w++) t += sm_s[w];
        const float loss = logf(t) - x[(size_t)row * N_COLS + tgt[row]];
        g_vals[row] = loss;
        const int q = quant(loss);
        atomicAdd(&g_fine[q], 1u);
        atomicAdd(&g_coarse[q >> 8], 1u);
    }
}

// ---------------------------------------------------------------------------
// Kernel 2: 32 blocks x 256 threads (single launch).
//  Phase 1: EVERY block redundantly scans coarse(256)+fine-stripe(256) bins
//           (L2-broadcast reads) -> (selbin, rem). No inter-block handoff.
//  Phase 2: one value/thread: above-bin fixed-point int64 sum (exact,
//           order-independent) + in-bin candidate compaction.
//  Phase 3: last block: radix-select among tiny candidate set in smem,
//           tie-exact mean, zero all hists + counters for next replay.
// ---------------------------------------------------------------------------
__global__ __launch_bounds__(256) void finish_kernel(float* __restrict__ out) {
    const int tid = threadIdx.x;
    const int bid = blockIdx.x;
    const int wid = tid >> 5;
    const int lane = tid & 31;

    __shared__ unsigned int wtot[8], woff[8];
    __shared__ unsigned int sel2[2];

    // ---- Phase 1a: redundant coarse scan (descending; thread t owns 255-t) ----
    unsigned int v = g_coarse[255 - tid];
    unsigned int pre = v;
    #pragma unroll
    for (int off = 1; off < 32; off <<= 1) {
        const unsigned int u = __shfl_up_sync(0xffffffffu, pre, off);
        if (lane >= off) pre += u;
    }
    if (lane == 31) wtot[wid] = pre;
    __syncthreads();
    if (tid == 0) {
        unsigned int a = 0;
        #pragma unroll
        for (int w = 0; w < 8; w++) { woff[w] = a; a += wtot[w]; }
    }
    __syncthreads();
    unsigned int excl = woff[wid] + (pre - v);
    if (excl < K2 && excl + v >= K2) {
        sel2[0] = (unsigned)(255 - tid);
        sel2[1] = K2 - excl;
    }
    __syncthreads();
    const unsigned int cb = sel2[0];
    const unsigned int remc = sel2[1];
    __syncthreads();

    // ---- Phase 1b: redundant fine scan inside coarse bin cb ----
    v = g_fine[cb * 256 + 255 - tid];
    pre = v;
    #pragma unroll
    for (int off = 1; off < 32; off <<= 1) {
        const unsigned int u = __shfl_up_sync(0xffffffffu, pre, off);
        if (lane >= off) pre += u;
    }
    if (lane == 31) wtot[wid] = pre;
    __syncthreads();
    if (tid == 0) {
        unsigned int a = 0;
        #pragma unroll
        for (int w = 0; w < 8; w++) { woff[w] = a; a += wtot[w]; }
    }
    __syncthreads();
    excl = woff[wid] + (pre - v);
    if (excl < remc && excl + v >= remc) {
        sel2[0] = (unsigned)(255 - tid);
        sel2[1] = remc - excl;
    }
    __syncthreads();
    const unsigned int selbin = cb * 256 + sel2[0];
    const unsigned int rem = sel2[1];

    // ---- Phase 2: process this block's 256 values ----
    const float val = g_vals[bid * 256 + tid];
    const int q = quant(val);
    long long loc = 0;
    if ((unsigned)q > selbin) loc = fixed_of(val);
    else if ((unsigned)q == selbin) g_cand[atomicAdd(&g_candcnt, 1u)] = val;

    #pragma unroll
    for (int off = 16; off; off >>= 1)
        loc += __shfl_down_sync(0xffffffffu, loc, off);
    __shared__ long long wsum[8];
    if (lane == 0) wsum[wid] = loc;
    __syncthreads();
    if (tid == 0) {
        long long s = 0;
        #pragma unroll
        for (int w = 0; w < 8; w++) s += wsum[w];
        atomicAdd(&g_sum, (unsigned long long)s);
    }

    __threadfence();
    __shared__ unsigned int sh_last;
    if (tid == 0)
        sh_last = (atomicAdd(&g_done, 1u) == (unsigned)(NB2B - 1)) ? 1u : 0u;
    __syncthreads();
    if (!sh_last) return;

    // ---------------- Phase 3: last block finishes ----------------
    __threadfence();
    const unsigned int C = *(volatile unsigned int*)&g_candcnt;   // >= rem

    __shared__ unsigned int skey[N_ROWS];   // worst-case capacity, 32 KB
    __shared__ unsigned int h2[256 * 4];
    for (unsigned int j = tid; j < C; j += 256) skey[j] = key_of(g_cand[j]);
    __syncthreads();

    // 4 x 8-bit MSB-first radix-select of the rem-th largest candidate
    unsigned int prefix = 0u, r = rem;
    #pragma unroll
    for (int shift = 24; shift >= 0; shift -= 8) {
        h2[tid] = 0u; h2[tid + 256] = 0u; h2[tid + 512] = 0u; h2[tid + 768] = 0u;
        __syncthreads();
        const unsigned int mask =
            (shift == 24) ? 0u : (0xFFFFFFFFu << (unsigned)(shift + 8));
        const int spread = tid & 3;
        for (unsigned int j = tid; j < C; j += 256) {
            const unsigned int k = skey[j];
            if ((k & mask) == prefix)
                atomicAdd(&h2[(((k >> shift) & 255u) << 2) + spread], 1u);
        }
        __syncthreads();
        if (wid == 0) {
            unsigned int hv[8], cs = 0u;
            #pragma unroll
            for (int j = 0; j < 8; j++) {
                const int b = 255 - lane * 8 - j;
                hv[j] = h2[(b << 2)] + h2[(b << 2) + 1] +
                        h2[(b << 2) + 2] + h2[(b << 2) + 3];
                cs += hv[j];
            }
            unsigned int pre2 = cs;
            #pragma unroll
            for (int off = 1; off < 32; off <<= 1) {
                const unsigned int u = __shfl_up_sync(0xffffffffu, pre2, off);
                if (lane >= off) pre2 += u;
            }
            unsigned int IS = pre2 - cs;
            #pragma unroll
            for (int j = 0; j < 8; j++) {
                const unsigned int lo = IS;
                IS += hv[j];
                if (IS >= r && lo < r) {
                    sel2[0] = (unsigned)(255 - lane * 8 - j);
                    sel2[1] = r - lo;
                }
            }
        }
        __syncthreads();
        prefix |= sel2[0] << (unsigned)shift;
        r = sel2[1];
        __syncthreads();
    }
    const unsigned int T = prefix;

    // tie-exact candidate sum (fixed point: deterministic)
    long long acc = 0; unsigned int cg = 0;
    for (unsigned int j = tid; j < C; j += 256) {
        const unsigned int k = skey[j];
        if (k > T) { acc += fixed_of(val_of(k)); cg++; }
    }
    #pragma unroll
    for (int off = 16; off; off >>= 1) {
        acc += __shfl_down_sync(0xffffffffu, acc, off);
        cg  += __shfl_down_sync(0xffffffffu, cg, off);
    }
    __shared__ long long fsum[8];
    __shared__ unsigned int fcnt[8];
    if (lane == 0) { fsum[wid] = acc; fcnt[wid] = cg; }
    __syncthreads();

    // zero all histograms for the next graph replay (256 KB + 1 KB)
    #pragma unroll 8
    for (int j = 0; j < NFINE / 256; j++)
        g_fine[j * 256 + tid] = 0u;
    g_coarse[tid] = 0u;

    if (tid == 0) {
        long long csum = 0; unsigned int ccnt = 0;
        #pragma unroll
        for (int w = 0; w < 8; w++) { csum += fsum[w]; ccnt += fcnt[w]; }
        const long long above = (long long)(*(volatile unsigned long long*)&g_sum);
        const long long total = above + csum +
            (long long)(rem - ccnt) * fixed_of(val_of(T));
        out[0] = (float)((double)total / 4294967296.0 / (double)K2);
        g_candcnt = 0u;
        g_done = 0u;
        g_sum = 0ull;
    }
}

// ---------------------------------------------------------------------------
extern "C" void kernel_launch(void* const* d_in, const int* in_sizes, int n_in,
                              void* d_out, int out_size) {
    const float* x   = (const float*)d_in[0];
    const int*   tgt = (const int*)d_in[1];
    float*       out = (float*)d_out;

    loss_kernel<<<N_ROWS, THREADS>>>(x, tgt);
    finish_kernel<<<NB2B, 256>>>(out);
}

// round 17
// speedup vs baseline: 1.0254x; 1.0254x over previous
#include <cuda_runtime.h>

#define N_ROWS  8192
#define N_COLS  32000
#define NV4     (N_COLS / 4)
#define K2      4915              // int(0.6 * int(1.0 * 8192))
#define THREADS 256
#define NBIN    1024              // 4 KB coarse hist, bin width 1/32 loss units
#define NBLK    32                // tail kernel blocks (32 x 256 = 8192)

// Scratch (device globals; reset each replay by tail kernel)
__device__ float              g_vals[N_ROWS];
__device__ unsigned int       g_hist[NBIN];
__device__ unsigned int       g_flag;            // 0 -> (selbin,rem) not ready
__device__ unsigned int       g_selbin, g_rem;
__device__ unsigned long long g_sum;             // fixed-point 2^32 above-bin sum
__device__ float              g_cand[N_ROWS];
__device__ unsigned int       g_candcnt;
__device__ unsigned int       g_done;

__device__ __forceinline__ int quant(float v) {
    int q = (int)(v * 32.0f);
    return max(0, min(q, NBIN - 1));
}
__device__ __forceinline__ unsigned int key_of(float f) {
    unsigned int u = __float_as_uint(f);
    return u ^ ((u & 0x80000000u) ? 0xFFFFFFFFu : 0x80000000u);
}
__device__ __forceinline__ float val_of(unsigned int k) {
    return __uint_as_float((k & 0x80000000u) ? (k ^ 0x80000000u) : ~k);
}
__device__ __forceinline__ long long fixed_of(float v) {
    return (long long)((double)v * 4294967296.0);   // exact, deterministic
}

// ---------------------------------------------------------------------------
// Kernel 1: one block per row, single-pass logsumexp loss (proven 90%-HBM
// mainloop, byte-identical). Tail: loss store + ONE 4KB-hist atomic.
// ---------------------------------------------------------------------------
__global__ __launch_bounds__(THREADS) void loss_kernel(const float* __restrict__ x,
                                                       const int* __restrict__ tgt) {
    const int row = blockIdx.x;
    const float4* __restrict__ rp =
        reinterpret_cast<const float4*>(x + (size_t)row * N_COLS);

    float s0 = 0.f, s1 = 0.f, s2 = 0.f, s3 = 0.f;
    int i = threadIdx.x;
    for (; i + 3 * THREADS < NV4; i += 4 * THREADS) {
        const float4 a = __ldcs(rp + i);
        const float4 b = __ldcs(rp + i + THREADS);
        const float4 c = __ldcs(rp + i + 2 * THREADS);
        const float4 d = __ldcs(rp + i + 3 * THREADS);
        s0 += (__expf(a.x) + __expf(a.y)) + (__expf(a.z) + __expf(a.w));
        s1 += (__expf(b.x) + __expf(b.y)) + (__expf(b.z) + __expf(b.w));
        s2 += (__expf(c.x) + __expf(c.y)) + (__expf(c.z) + __expf(c.w));
        s3 += (__expf(d.x) + __expf(d.y)) + (__expf(d.z) + __expf(d.w));
    }
    for (; i < NV4; i += THREADS) {
        const float4 a = __ldcs(rp + i);
        s0 += (__expf(a.x) + __expf(a.y)) + (__expf(a.z) + __expf(a.w));
    }

    float s = (s0 + s1) + (s2 + s3);
    #pragma unroll
    for (int off = 16; off; off >>= 1)
        s += __shfl_xor_sync(0xffffffffu, s, off);

    __shared__ float sm_s[THREADS / 32];
    const int warp = threadIdx.x >> 5;
    const int lane = threadIdx.x & 31;
    if (lane == 0) sm_s[warp] = s;
    __syncthreads();

    if (threadIdx.x == 0) {
        float t = 0.f;
        #pragma unroll
        for (int w = 0; w < THREADS / 32; w++) t += sm_s[w];
        const float loss = logf(t) - x[(size_t)row * N_COLS + tgt[row]];
        g_vals[row] = loss;
        atomicAdd(&g_hist[quant(loss)], 1u);
    }
}

// ---------------------------------------------------------------------------
// Kernel 2: 32 blocks x 256 threads, single launch.
//  Block 0: scan 1024-bin hist (zero as read) -> publish (selbin, rem).
//  Blocks 1..31: prefetch their 256 losses into regs, spin on flag (overlap!).
//  All blocks: above-bin fixed-point sum (one atomic/blk) + warp-aggregated
//  candidate compaction. Last block: smem radix-select + tie-exact mean,
//  reset all replay state.
// ---------------------------------------------------------------------------
__global__ __launch_bounds__(256) void finish_kernel(float* __restrict__ out) {
    const int tid = threadIdx.x;
    const int bid = blockIdx.x;
    const int wid = tid >> 5;
    const int lane = tid & 31;

    // Prefetch this thread's value FIRST: DRAM latency overlaps block 0's scan.
    const float val = g_vals[bid * 256 + tid];

    __shared__ unsigned int sh_sb, sh_rem;
    __shared__ unsigned int wtot[8], woff[8];
    __shared__ unsigned int sel2[2];

    unsigned int selbin, rem;
    if (bid == 0) {
        // ---- scan 1024 bins descending: thread t owns bins 1023-4t .. -3 ----
        unsigned int hv[4], csum = 0u;
        const int base = NBIN - 1 - tid * 4;
        #pragma unroll
        for (int j = 0; j < 4; j++) {
            hv[j] = g_hist[base - j];
            g_hist[base - j] = 0u;            // restore for next replay
            csum += hv[j];
        }
        unsigned int pre = csum;
        #pragma unroll
        for (int off = 1; off < 32; off <<= 1) {
            const unsigned int u = __shfl_up_sync(0xffffffffu, pre, off);
            if (lane >= off) pre += u;
        }
        if (lane == 31) wtot[wid] = pre;
        __syncthreads();
        if (tid == 0) {
            unsigned int a = 0;
            #pragma unroll
            for (int w = 0; w < 8; w++) { woff[w] = a; a += wtot[w]; }
        }
        __syncthreads();
        unsigned int IS = woff[wid] + (pre - csum);
        #pragma unroll
        for (int j = 0; j < 4; j++) {
            const unsigned int lo = IS;
            IS += hv[j];
            if (IS >= K2 && lo < K2) { sel2[0] = (unsigned)(base - j); sel2[1] = K2 - lo; }
        }
        __syncthreads();
        if (tid == 0) {
            g_selbin = sel2[0];
            g_rem = sel2[1];
            __threadfence();
            atomicExch(&g_flag, 1u);          // release publish
        }
        selbin = sel2[0];
        rem = sel2[1];
    } else {
        if (tid == 0) {
            while (atomicAdd(&g_flag, 0u) == 0u) __nanosleep(64);
            __threadfence();                  // acquire
            sh_sb = g_selbin;
            sh_rem = g_rem;
        }
        __syncthreads();
        selbin = sh_sb;
        rem = sh_rem;
    }

    // ---- process this thread's value ----
    const int q = quant(val);
    long long loc = ((unsigned)q > selbin) ? fixed_of(val) : 0;

    const bool isCand = ((unsigned)q == selbin);
    const unsigned int ball = __ballot_sync(0xffffffffu, isCand);
    if (ball) {                               // warp-aggregated compaction
        const int leader = __ffs(ball) - 1;
        unsigned int base = 0;
        if (lane == leader) base = atomicAdd(&g_candcnt, (unsigned)__popc(ball));
        base = __shfl_sync(0xffffffffu, base, leader);
        if (isCand)
            g_cand[base + __popc(ball & ((1u << lane) - 1u))] = val;
    }

    #pragma unroll
    for (int off = 16; off; off >>= 1)
        loc += __shfl_down_sync(0xffffffffu, loc, off);
    __shared__ long long wsum[8];
    if (lane == 0) wsum[wid] = loc;
    __syncthreads();
    if (tid == 0) {
        long long s = 0;
        #pragma unroll
        for (int w = 0; w < 8; w++) s += wsum[w];
        atomicAdd(&g_sum, (unsigned long long)s);
    }

    __threadfence();
    __shared__ unsigned int sh_last;
    if (tid == 0)
        sh_last = (atomicAdd(&g_done, 1u) == (unsigned)(NBLK - 1)) ? 1u : 0u;
    __syncthreads();
    if (!sh_last) return;

    // ---------------- last block: finish ----------------
    __threadfence();
    const unsigned int C = *(volatile unsigned int*)&g_candcnt;   // >= rem

    __shared__ unsigned int skey[N_ROWS];   // worst-case capacity, 32 KB
    __shared__ unsigned int h2[256 * 4];
    for (unsigned int j = tid; j < C; j += 256) skey[j] = key_of(g_cand[j]);
    __syncthreads();

    // 4 x 8-bit MSB-first radix-select of the rem-th largest candidate
    unsigned int prefix = 0u, r = rem;
    #pragma unroll
    for (int shift = 24; shift >= 0; shift -= 8) {
        h2[tid] = 0u; h2[tid + 256] = 0u; h2[tid + 512] = 0u; h2[tid + 768] = 0u;
        __syncthreads();
        const unsigned int mask =
            (shift == 24) ? 0u : (0xFFFFFFFFu << (unsigned)(shift + 8));
        const int spread = tid & 3;
        for (unsigned int j = tid; j < C; j += 256) {
            const unsigned int k = skey[j];
            if ((k & mask) == prefix)
                atomicAdd(&h2[(((k >> shift) & 255u) << 2) + spread], 1u);
        }
        __syncthreads();
        if (wid == 0) {                       // descending scan, 8 bins/lane
            unsigned int hv[8], cs = 0u;
            #pragma unroll
            for (int j = 0; j < 8; j++) {
                const int b = 255 - lane * 8 - j;
                hv[j] = h2[(b << 2)] + h2[(b << 2) + 1] +
                        h2[(b << 2) + 2] + h2[(b << 2) + 3];
                cs += hv[j];
            }
            unsigned int pre2 = cs;
            #pragma unroll
            for (int off = 1; off < 32; off <<= 1) {
                const unsigned int u = __shfl_up_sync(0xffffffffu, pre2, off);
                if (lane >= off) pre2 += u;
            }
            unsigned int IS = pre2 - cs;
            #pragma unroll
            for (int j = 0; j < 8; j++) {
                const unsigned int lo = IS;
                IS += hv[j];
                if (IS >= r && lo < r) {
                    sel2[0] = (unsigned)(255 - lane * 8 - j);
                    sel2[1] = r - lo;
                }
            }
        }
        __syncthreads();
        prefix |= sel2[0] << (unsigned)shift;
        r = sel2[1];
        __syncthreads();
    }
    const unsigned int T = prefix;

    // tie-exact candidate sum (fixed point: deterministic)
    long long acc = 0; unsigned int cg = 0;
    for (unsigned int j = tid; j < C; j += 256) {
        const unsigned int k = skey[j];
        if (k > T) { acc += fixed_of(val_of(k)); cg++; }
    }
    #pragma unroll
    for (int off = 16; off; off >>= 1) {
        acc += __shfl_down_sync(0xffffffffu, acc, off);
        cg  += __shfl_down_sync(0xffffffffu, cg, off);
    }
    __shared__ long long fsum[8];
    __shared__ unsigned int fcnt[8];
    if (lane == 0) { fsum[wid] = acc; fcnt[wid] = cg; }
    __syncthreads();

    if (tid == 0) {
        long long csum = 0; unsigned int ccnt = 0;
        #pragma unroll
        for (int w = 0; w < 8; w++) { csum += fsum[w]; ccnt += fcnt[w]; }
        const long long above = (long long)(*(volatile unsigned long long*)&g_sum);
        const long long total = above + csum +
            (long long)(rem - ccnt) * fixed_of(val_of(T));
        out[0] = (float)((double)total / 4294967296.0 / (double)K2);
        // reset replay state (hist already zeroed by block 0)
        g_candcnt = 0u;
        g_done = 0u;
        g_sum = 0ull;
        g_flag = 0u;
    }
}

// ---------------------------------------------------------------------------
extern "C" void kernel_launch(void* const* d_in, const int* in_sizes, int n_in,
                              void* d_out, int out_size) {
    const float* x   = (const float*)d_in[0];
    const int*   tgt = (const int*)d_in[1];
    float*       out = (float*)d_out;

    loss_kernel<<<N_ROWS, THREADS>>>(x, tgt);
    finish_kernel<<<NBLK, 256>>>(out);
}